// round 1
// baseline (speedup 1.0000x reference)
#include <cuda_runtime.h>

#define LRATE 0.25f
#define NIT 20
#define NMOM 42
#define MPAD 48

// Persistent device scratch (allowed; fully rewritten deterministically each launch)
__device__ float gM[NIT + 1][MPAD];      // moments per iteration (zeroed each launch)
__device__ float gTheta[NIT + 1][12];    // theta trajectory
__device__ float gLam[NIT][12];          // adjoints: gLam[k] = lambda_{k+1}

// theta layout [12]: t1 (0..3 row-major), b1 (4,5), t2 (6..9 row-major), b2 (10,11)
// moments layout [42]:
//  0..3   M1_{ab} = sum p_a h_b           (idx 2a+b)
//  4..7   M2_{ab} = sum p_a s_b
//  8..15  M3_{abc}= sum p_a s_b z_c       (idx 4a+2b+c)
// 16..19  M4_{ab} = sum p_a h_b s_b
// 20..27  M5_{abc}= sum p_a h_b s_b z_c
// 28..39  M6_{ab,(ce)} = sum p_a h_b s_b z_c z_e, sym pair idx (c+e): 28+(2a+b)*3+(c+e)
// 40..41  Sp_a    = sum p_a

__device__ __forceinline__ float ftanh(float x) {
    // accurate fast tanh: tanh(x) = sign(x)*(1-e)/(1+e), e = exp(-2|x|)
    float e = __expf(-2.0f * fabsf(x));
    float r = __fdividef(1.0f - e, 1.0f + e);
    return copysignf(r, x);
}

__device__ __forceinline__ void sym4mv(const float* __restrict__ A, const float* v, float* y) {
#pragma unroll
    for (int r = 0; r < 4; ++r) {
        float s = 0.f;
#pragma unroll
        for (int c = 0; c < 4; ++c) s += 0.5f * (A[4 * r + c] + A[4 * c + r]) * v[c];
        y[r] = s;
    }
}

__device__ __forceinline__ void sym2mv(const float* __restrict__ A, const float* v, float* y) {
#pragma unroll
    for (int r = 0; r < 2; ++r) {
        float s = 0.f;
#pragma unroll
        for (int c = 0; c < 2; ++c) s += 0.5f * (A[2 * r + c] + A[2 * c + r]) * v[c];
        y[r] = s;
    }
}

// G = dL/dtheta from moments M evaluated at theta th
__device__ __forceinline__ void compute_G(const float* th, const float* M,
                                          const float* __restrict__ invK,
                                          const float* __restrict__ invKb,
                                          float inv2K, float* G) {
    float y[4], yb[2];
    // t1 block
    sym4mv(invK, th, y);
#pragma unroll
    for (int r = 0; r < 4; ++r) G[r] = y[r] - inv2K * M[r];
    // b1 block
    sym2mv(invKb, th + 4, yb);
    G[4] = yb[0] - inv2K * M[40];
    G[5] = yb[1] - inv2K * M[41];
    // t2 block (kinetic uses t2 - I)
    float v2[4] = {th[6] - 1.f, th[7], th[8], th[9] - 1.f};
    sym4mv(invK, v2, y);
#pragma unroll
    for (int b = 0; b < 2; ++b)
#pragma unroll
        for (int c = 0; c < 2; ++c) {
            float pot = th[b] * M[8 + 2 * b + c] + th[2 + b] * M[8 + 4 + 2 * b + c];
            G[6 + 2 * b + c] = y[2 * b + c] - inv2K * pot;
        }
    // b2 block
    sym2mv(invKb, th + 10, yb);
#pragma unroll
    for (int b = 0; b < 2; ++b) {
        float pot = th[b] * M[4 + b] + th[2 + b] * M[4 + 2 + b];
        G[10 + b] = yb[b] - inv2K * pot;
    }
}

__global__ void zero_moments_kernel() {
    int t = blockIdx.x * blockDim.x + threadIdx.x;
    if (t < (NIT + 1) * MPAD) ((float*)gM)[t] = 0.f;
}

__global__ void pass_kernel(const float* __restrict__ inp,
                            const float* __restrict__ t1i, const float* __restrict__ b1i,
                            const float* __restrict__ t2i, const float* __restrict__ b2i,
                            const float* __restrict__ invK, const float* __restrict__ invKb,
                            int K, int k) {
    __shared__ float sTh[12];
    __shared__ float sred[NMOM];

    if (threadIdx.x == 0) {
        float th[12];
        if (k == 0) {
            th[0] = t1i[0]; th[1] = t1i[1]; th[2] = t1i[2]; th[3] = t1i[3];
            th[4] = b1i[0]; th[5] = b1i[1];
            th[6] = t2i[0]; th[7] = t2i[1]; th[8] = t2i[2]; th[9] = t2i[3];
            th[10] = b2i[0]; th[11] = b2i[1];
        } else {
            float pth[12], G[12];
#pragma unroll
            for (int j = 0; j < 12; ++j) pth[j] = gTheta[k - 1][j];
            compute_G(pth, gM[k - 1], invK, invKb, 0.5f / (float)K, G);
#pragma unroll
            for (int j = 0; j < 12; ++j) th[j] = pth[j] - LRATE * G[j];
        }
#pragma unroll
        for (int j = 0; j < 12; ++j) { sTh[j] = th[j]; gTheta[k][j] = th[j]; }
    }
    if (threadIdx.x < NMOM) sred[threadIdx.x] = 0.f;
    __syncthreads();

    const float c20 = sTh[6], c21 = sTh[7], c22 = sTh[8], c23 = sTh[9];
    const float d0 = sTh[10], d1 = sTh[11];

    float acc[NMOM];
#pragma unroll
    for (int j = 0; j < NMOM; ++j) acc[j] = 0.f;

    const float2* z2 = (const float2*)inp;
    const int stride = gridDim.x * blockDim.x;
    for (int i = blockIdx.x * blockDim.x + threadIdx.x; i < K; i += stride) {
        float2 z = z2[i];
        float2 p = z2[K + i];
        float u0 = fmaf(c20, z.x, fmaf(c21, z.y, d0));
        float u1 = fmaf(c22, z.x, fmaf(c23, z.y, d1));
        float h0 = ftanh(u0), h1 = ftanh(u1);
        float s0 = fmaf(-h0, h0, 1.f), s1 = fmaf(-h1, h1, 1.f);
        float hs0 = h0 * s0, hs1 = h1 * s1;
        float zz0 = z.x * z.x, zz1 = z.x * z.y, zz2 = z.y * z.y;
        float pv[2] = {p.x, p.y};
#pragma unroll
        for (int a = 0; a < 2; ++a) {
            float pa = pv[a];
            float ps0 = pa * s0, ps1 = pa * s1;
            float ph0 = pa * hs0, ph1 = pa * hs1;
            acc[0 + 2 * a + 0] = fmaf(pa, h0, acc[0 + 2 * a + 0]);
            acc[0 + 2 * a + 1] = fmaf(pa, h1, acc[0 + 2 * a + 1]);
            acc[4 + 2 * a + 0] += ps0;
            acc[4 + 2 * a + 1] += ps1;
            acc[8 + 4 * a + 0] = fmaf(ps0, z.x, acc[8 + 4 * a + 0]);
            acc[8 + 4 * a + 1] = fmaf(ps0, z.y, acc[8 + 4 * a + 1]);
            acc[8 + 4 * a + 2] = fmaf(ps1, z.x, acc[8 + 4 * a + 2]);
            acc[8 + 4 * a + 3] = fmaf(ps1, z.y, acc[8 + 4 * a + 3]);
            acc[16 + 2 * a + 0] += ph0;
            acc[16 + 2 * a + 1] += ph1;
            acc[20 + 4 * a + 0] = fmaf(ph0, z.x, acc[20 + 4 * a + 0]);
            acc[20 + 4 * a + 1] = fmaf(ph0, z.y, acc[20 + 4 * a + 1]);
            acc[20 + 4 * a + 2] = fmaf(ph1, z.x, acc[20 + 4 * a + 2]);
            acc[20 + 4 * a + 3] = fmaf(ph1, z.y, acc[20 + 4 * a + 3]);
            acc[28 + 6 * a + 0] = fmaf(ph0, zz0, acc[28 + 6 * a + 0]);
            acc[28 + 6 * a + 1] = fmaf(ph0, zz1, acc[28 + 6 * a + 1]);
            acc[28 + 6 * a + 2] = fmaf(ph0, zz2, acc[28 + 6 * a + 2]);
            acc[28 + 6 * a + 3] = fmaf(ph1, zz0, acc[28 + 6 * a + 3]);
            acc[28 + 6 * a + 4] = fmaf(ph1, zz1, acc[28 + 6 * a + 4]);
            acc[28 + 6 * a + 5] = fmaf(ph1, zz2, acc[28 + 6 * a + 5]);
            acc[40 + a] += pa;
        }
    }

    // warp tree-reduce each moment
#pragma unroll
    for (int j = 0; j < NMOM; ++j) {
#pragma unroll
        for (int off = 16; off > 0; off >>= 1)
            acc[j] += __shfl_down_sync(0xffffffffu, acc[j], off);
    }
    if ((threadIdx.x & 31) == 0) {
#pragma unroll
        for (int j = 0; j < NMOM; ++j) atomicAdd(&sred[j], acc[j]);
    }
    __syncthreads();
    if (threadIdx.x < NMOM) atomicAdd(&gM[k][threadIdx.x], sred[threadIdx.x]);
}

__global__ void backward_kernel(const float* __restrict__ invK,
                                const float* __restrict__ invKb, int K) {
    if (blockIdx.x != 0 || threadIdx.x != 0) return;
    const float inv2K = 0.5f / (float)K;
    float lam[12];
    compute_G(gTheta[NIT], gM[NIT], invK, invKb, inv2K, lam);  // lambda_20
    for (int k = NIT - 1; k >= 0; --k) {
#pragma unroll
        for (int j = 0; j < 12; ++j) gLam[k][j] = lam[j];
        if (k > 0) {
            const float* M = gM[k];
            const float* th = gTheta[k];
            float y[12], t4[4], tb[2];
            sym4mv(invK, lam, t4);      y[0]=t4[0]; y[1]=t4[1]; y[2]=t4[2]; y[3]=t4[3];
            sym2mv(invKb, lam + 4, tb); y[4]=tb[0]; y[5]=tb[1];
            sym4mv(invK, lam + 6, t4);  y[6]=t4[0]; y[7]=t4[1]; y[8]=t4[2]; y[9]=t4[3];
            sym2mv(invKb, lam + 10, tb);y[10]=tb[0]; y[11]=tb[1];

            float PL[12];
#pragma unroll
            for (int a = 0; a < 2; ++a)
#pragma unroll
                for (int b = 0; b < 2; ++b)
                    PL[2 * a + b] = M[8 + 4 * a + 2 * b + 0] * lam[6 + 2 * b + 0]
                                  + M[8 + 4 * a + 2 * b + 1] * lam[6 + 2 * b + 1]
                                  + M[4 + 2 * a + b] * lam[10 + b];
            PL[4] = 0.f; PL[5] = 0.f;

            float T4[2], T5[4], T6[6];
#pragma unroll
            for (int b = 0; b < 2; ++b) {
                T4[b] = th[b] * M[16 + b] + th[2 + b] * M[16 + 2 + b];
#pragma unroll
                for (int c = 0; c < 2; ++c)
                    T5[2 * b + c] = th[b] * M[20 + 2 * b + c] + th[2 + b] * M[20 + 4 + 2 * b + c];
#pragma unroll
                for (int t6 = 0; t6 < 3; ++t6)
                    T6[3 * b + t6] = th[b] * M[28 + 3 * b + t6] + th[2 + b] * M[28 + 3 * (2 + b) + t6];
            }
#pragma unroll
            for (int b = 0; b < 2; ++b)
#pragma unroll
                for (int c = 0; c < 2; ++c) {
                    float v = lam[b] * M[8 + 2 * b + c] + lam[2 + b] * M[8 + 4 + 2 * b + c];
                    v -= 2.f * (T6[3 * b + c + 0] * lam[6 + 2 * b + 0] +
                                T6[3 * b + c + 1] * lam[6 + 2 * b + 1]);
                    v -= 2.f * T5[2 * b + c] * lam[10 + b];
                    PL[6 + 2 * b + c] = v;
                }
#pragma unroll
            for (int b = 0; b < 2; ++b) {
                float v = lam[b] * M[4 + b] + lam[2 + b] * M[4 + 2 + b];
                v -= 2.f * (T5[2 * b + 0] * lam[6 + 2 * b + 0] +
                            T5[2 * b + 1] * lam[6 + 2 * b + 1]);
                v -= 2.f * T4[b] * lam[10 + b];
                PL[10 + b] = v;
            }
#pragma unroll
            for (int j = 0; j < 12; ++j) lam[j] -= LRATE * (y[j] - inv2K * PL[j]);
        }
    }
}

#define PC_P 4
__global__ void phasec_kernel(const float* __restrict__ inp, float* __restrict__ out, int K) {
    __shared__ float sTh[(NIT + 1) * 12];
    __shared__ float sLam[NIT * 12];
    for (int j = threadIdx.x; j < (NIT + 1) * 12; j += blockDim.x) sTh[j] = ((const float*)gTheta)[j];
    for (int j = threadIdx.x; j < NIT * 12; j += blockDim.x) sLam[j] = ((const float*)gLam)[j];
    __syncthreads();

    const float inv2K = 0.5f / (float)K;
    const float2* z2 = (const float2*)inp;
    float2* o2 = (float2*)out;
    const int base = blockIdx.x * (blockDim.x * PC_P) + threadIdx.x;

    float zx[PC_P], zy[PC_P], px[PC_P], py[PC_P], ax[PC_P], ay[PC_P];
#pragma unroll
    for (int j = 0; j < PC_P; ++j) {
        int i = base + j * blockDim.x;
        if (i < K) {
            float2 z = z2[i]; zx[j] = z.x; zy[j] = z.y;
            float2 p = z2[K + i]; px[j] = p.x; py[j] = p.y;
        } else { zx[j] = zy[j] = px[j] = py[j] = 0.f; }
        ax[j] = ay[j] = 0.f;
    }

    for (int k = 0; k < NIT; ++k) {
        const float* th = &sTh[12 * k];
        const float* L = &sLam[12 * k];
        float a0 = th[0], a1 = th[1], a2 = th[2], a3 = th[3];
        float c0 = th[6], c1 = th[7], c2 = th[8], c3 = th[9], d0 = th[10], d1 = th[11];
        float l0 = L[0], l1 = L[1], l2 = L[2], l3 = L[3];
        float q0 = L[6], q1 = L[7], q2 = L[8], q3 = L[9], r0 = L[10], r1 = L[11];
#pragma unroll
        for (int j = 0; j < PC_P; ++j) {
            float u0 = fmaf(c0, zx[j], fmaf(c1, zy[j], d0));
            float u1 = fmaf(c2, zx[j], fmaf(c3, zy[j], d1));
            float h0 = ftanh(u0), h1 = ftanh(u1);
            float s0 = fmaf(-h0, h0, 1.f), s1 = fmaf(-h1, h1, 1.f);
            float w0 = fmaf(a0, px[j], a2 * py[j]);
            float w1 = fmaf(a1, px[j], a3 * py[j]);
            float m0 = fmaf(l0, px[j], l2 * py[j]);
            float m1 = fmaf(l1, px[j], l3 * py[j]);
            float k0 = fmaf(q0, zx[j], fmaf(q1, zy[j], r0));
            float k1 = fmaf(q2, zx[j], fmaf(q3, zy[j], r1));
            float wh0 = w0 * h0, wh1 = w1 * h1;
            float e0 = s0 * fmaf(-2.f * wh0, k0, m0);
            float e1 = s1 * fmaf(-2.f * wh1, k1, m1);
            float ws0 = w0 * s0, ws1 = w1 * s1;
            ax[j] += e0 * c0 + e1 * c2 + q0 * ws0 + q2 * ws1;
            ay[j] += e0 * c1 + e1 * c3 + q1 * ws0 + q3 * ws1;
        }
    }

    {
        const float* th = &sTh[12 * NIT];
        float a0 = th[0], a1 = th[1], a2 = th[2], a3 = th[3], b0 = th[4], b1v = th[5];
        float c0 = th[6], c1 = th[7], c2 = th[8], c3 = th[9], d0 = th[10], d1 = th[11];
#pragma unroll
        for (int j = 0; j < PC_P; ++j) {
            int i = base + j * blockDim.x;
            if (i >= K) continue;
            float u0 = fmaf(c0, zx[j], fmaf(c1, zy[j], d0));
            float u1 = fmaf(c2, zx[j], fmaf(c3, zy[j], d1));
            float h0 = ftanh(u0), h1 = ftanh(u1);
            float s0 = fmaf(-h0, h0, 1.f), s1 = fmaf(-h1, h1, 1.f);
            float w0 = fmaf(a0, px[j], a2 * py[j]);
            float w1 = fmaf(a1, px[j], a3 * py[j]);
            float ws0 = w0 * s0, ws1 = w1 * s1;
            float dpx = inv2K * (LRATE * ax[j] - (ws0 * c0 + ws1 * c2));
            float dpy = inv2K * (LRATE * ay[j] - (ws0 * c1 + ws1 * c3));
            float dqx = fmaf(a0, h0, fmaf(a1, h1, b0));
            float dqy = fmaf(a2, h0, fmaf(a3, h1, b1v));
            o2[i] = make_float2(dqx, dqy);
            o2[K + i] = make_float2(dpx, dpy);
            float2 xv = z2[2 * K + i];
            float v0 = fmaf(c0, xv.x, fmaf(c1, xv.y, d0));
            float v1 = fmaf(c2, xv.x, fmaf(c3, xv.y, d1));
            float g0 = ftanh(v0), g1 = ftanh(v1);
            float dxx = fmaf(a0, g0, fmaf(a1, g1, b0));
            float dxy = fmaf(a2, g0, fmaf(a3, g1, b1v));
            o2[2 * K + i] = make_float2(dxx, dxy);
        }
    }
}

extern "C" void kernel_launch(void* const* d_in, const int* in_sizes, int n_in,
                              void* d_out, int out_size) {
    (void)n_in; (void)out_size;
    const float* inp  = (const float*)d_in[1];
    const float* t1i  = (const float*)d_in[2];
    const float* b1i  = (const float*)d_in[3];
    const float* t2i  = (const float*)d_in[4];
    const float* b2i  = (const float*)d_in[5];
    const float* invK = (const float*)d_in[6];
    const float* invKb= (const float*)d_in[7];
    int K = in_sizes[1] / 6;

    zero_moments_kernel<<<((NIT + 1) * MPAD + 255) / 256, 256>>>();
    for (int k = 0; k <= NIT; ++k)
        pass_kernel<<<304, 256>>>(inp, t1i, b1i, t2i, b2i, invK, invKb, K, k);
    backward_kernel<<<1, 1>>>(invK, invKb, K);
    int blocks = (K + 256 * PC_P - 1) / (256 * PC_P);
    phasec_kernel<<<blocks, 256>>>(inp, (float*)d_out, K);
}

// round 2
// speedup vs baseline: 1.0015x; 1.0015x over previous
#include <cuda_runtime.h>

#define LRATE 0.25f
#define NIT 20
#define NMOM 42
#define MPAD 48

typedef unsigned long long u64;

// Persistent device scratch (rewritten deterministically every launch)
__device__ float gM[NIT + 1][MPAD];      // moments per iteration
__device__ float gTheta[NIT + 1][12];    // theta trajectory
__device__ float gLam[NIT][12];          // adjoints: gLam[k] = lambda_{k+1}

// ---------------- packed f32x2 helpers (Blackwell FFMA2 path) ----------------
__device__ __forceinline__ u64 f2pack(float lo, float hi) {
    u64 r; asm("mov.b64 %0, {%1, %2};" : "=l"(r) : "f"(lo), "f"(hi)); return r;
}
__device__ __forceinline__ void f2unpack(u64 v, float& lo, float& hi) {
    asm("mov.b64 {%0, %1}, %2;" : "=f"(lo), "=f"(hi) : "l"(v));
}
__device__ __forceinline__ u64 f2bcast(float x) { return f2pack(x, x); }
__device__ __forceinline__ u64 f2fma(u64 a, u64 b, u64 c) {
    u64 d; asm("fma.rn.f32x2 %0, %1, %2, %3;" : "=l"(d) : "l"(a), "l"(b), "l"(c)); return d;
}
__device__ __forceinline__ u64 f2mul(u64 a, u64 b) {
    u64 d; asm("mul.rn.f32x2 %0, %1, %2;" : "=l"(d) : "l"(a), "l"(b)); return d;
}
__device__ __forceinline__ u64 f2add(u64 a, u64 b) {
    u64 d; asm("add.rn.f32x2 %0, %1, %2;" : "=l"(d) : "l"(a), "l"(b)); return d;
}
__device__ __forceinline__ u64 f2neg(u64 a) { return a ^ 0x8000000080000000ULL; }

__device__ __forceinline__ float ftanh(float x) {
    float e = __expf(-2.0f * fabsf(x));
    float r = __fdividef(1.0f - e, 1.0f + e);
    return copysignf(r, x);
}
__device__ __forceinline__ u64 ftanh2(u64 u) {
    float a, b; f2unpack(u, a, b);
    return f2pack(ftanh(a), ftanh(b));
}

// ---------------- small symmetric mat-vec helpers ----------------
__device__ __forceinline__ void sym4mv(const float* __restrict__ A, const float* v, float* y) {
#pragma unroll
    for (int r = 0; r < 4; ++r) {
        float s = 0.f;
#pragma unroll
        for (int c = 0; c < 4; ++c) s += 0.5f * (A[4 * r + c] + A[4 * c + r]) * v[c];
        y[r] = s;
    }
}
__device__ __forceinline__ void sym2mv(const float* __restrict__ A, const float* v, float* y) {
#pragma unroll
    for (int r = 0; r < 2; ++r) {
        float s = 0.f;
#pragma unroll
        for (int c = 0; c < 2; ++c) s += 0.5f * (A[2 * r + c] + A[2 * c + r]) * v[c];
        y[r] = s;
    }
}

// G = dL/dtheta from moments M at theta th
__device__ __forceinline__ void compute_G(const float* th, const float* M,
                                          const float* __restrict__ invK,
                                          const float* __restrict__ invKb,
                                          float inv2K, float* G) {
    float y[4], yb[2];
    sym4mv(invK, th, y);
#pragma unroll
    for (int r = 0; r < 4; ++r) G[r] = y[r] - inv2K * M[r];
    sym2mv(invKb, th + 4, yb);
    G[4] = yb[0] - inv2K * M[40];
    G[5] = yb[1] - inv2K * M[41];
    float v2[4] = {th[6] - 1.f, th[7], th[8], th[9] - 1.f};
    sym4mv(invK, v2, y);
#pragma unroll
    for (int b = 0; b < 2; ++b)
#pragma unroll
        for (int c = 0; c < 2; ++c) {
            float pot = th[b] * M[8 + 2 * b + c] + th[2 + b] * M[8 + 4 + 2 * b + c];
            G[6 + 2 * b + c] = y[2 * b + c] - inv2K * pot;
        }
    sym2mv(invKb, th + 10, yb);
#pragma unroll
    for (int b = 0; b < 2; ++b) {
        float pot = th[b] * M[4 + b] + th[2 + b] * M[4 + 2 + b];
        G[10 + b] = yb[b] - inv2K * pot;
    }
}

__global__ void zero_moments_kernel() {
    int t = blockIdx.x * blockDim.x + threadIdx.x;
    if (t < (NIT + 1) * MPAD) ((float*)gM)[t] = 0.f;
}

// ---------------- pass: fused theta-update + packed moment accumulation ----------------
__global__ void __launch_bounds__(128, 3)
pass_kernel(const float* __restrict__ inp,
            const float* __restrict__ t1i, const float* __restrict__ b1i,
            const float* __restrict__ t2i, const float* __restrict__ b2i,
            const float* __restrict__ invK, const float* __restrict__ invKb,
            int K, int k) {
    __shared__ float sTh[12];
    __shared__ float sred[NMOM];

    if (threadIdx.x == 0) {
        float th[12];
        if (k == 0) {
            th[0] = t1i[0]; th[1] = t1i[1]; th[2] = t1i[2]; th[3] = t1i[3];
            th[4] = b1i[0]; th[5] = b1i[1];
            th[6] = t2i[0]; th[7] = t2i[1]; th[8] = t2i[2]; th[9] = t2i[3];
            th[10] = b2i[0]; th[11] = b2i[1];
        } else {
            float pth[12], G[12];
#pragma unroll
            for (int j = 0; j < 12; ++j) pth[j] = gTheta[k - 1][j];
            compute_G(pth, gM[k - 1], invK, invKb, 0.5f / (float)K, G);
#pragma unroll
            for (int j = 0; j < 12; ++j) th[j] = pth[j] - LRATE * G[j];
        }
#pragma unroll
        for (int j = 0; j < 12; ++j) { sTh[j] = th[j]; gTheta[k][j] = th[j]; }
    }
    if (threadIdx.x < NMOM) sred[threadIdx.x] = 0.f;
    __syncthreads();

    const u64 c20 = f2bcast(sTh[6]), c21 = f2bcast(sTh[7]);
    const u64 c22 = f2bcast(sTh[8]), c23 = f2bcast(sTh[9]);
    const u64 d0 = f2bcast(sTh[10]), d1 = f2bcast(sTh[11]);
    const u64 one2 = f2bcast(1.f);

    u64 acc[NMOM];
#pragma unroll
    for (int j = 0; j < NMOM; ++j) acc[j] = 0ULL;

    const float4* q4 = (const float4*)inp;
    const float4* p4 = (const float4*)(inp + 2 * (size_t)K);
    const int npair = K >> 1;
    const int stride = gridDim.x * blockDim.x;
    for (int t = blockIdx.x * blockDim.x + threadIdx.x; t < npair; t += stride) {
        float4 qa = q4[t];
        float4 pp = p4[t];
        u64 zx = f2pack(qa.x, qa.z), zy = f2pack(qa.y, qa.w);
        u64 px = f2pack(pp.x, pp.z), py = f2pack(pp.y, pp.w);
        u64 u0 = f2fma(c20, zx, f2fma(c21, zy, d0));
        u64 u1 = f2fma(c22, zx, f2fma(c23, zy, d1));
        u64 h0 = ftanh2(u0), h1 = ftanh2(u1);
        u64 s0 = f2fma(f2neg(h0), h0, one2), s1 = f2fma(f2neg(h1), h1, one2);
        u64 hs0 = f2mul(h0, s0), hs1 = f2mul(h1, s1);
        u64 zz0 = f2mul(zx, zx), zz1 = f2mul(zx, zy), zz2 = f2mul(zy, zy);
#pragma unroll
        for (int a = 0; a < 2; ++a) {
            u64 pv = a ? py : px;
            u64 ps0 = f2mul(pv, s0), ps1 = f2mul(pv, s1);
            u64 ph0 = f2mul(pv, hs0), ph1 = f2mul(pv, hs1);
            acc[0 + 2 * a + 0] = f2fma(pv, h0, acc[0 + 2 * a + 0]);
            acc[0 + 2 * a + 1] = f2fma(pv, h1, acc[0 + 2 * a + 1]);
            acc[4 + 2 * a + 0] = f2add(acc[4 + 2 * a + 0], ps0);
            acc[4 + 2 * a + 1] = f2add(acc[4 + 2 * a + 1], ps1);
            acc[8 + 4 * a + 0] = f2fma(ps0, zx, acc[8 + 4 * a + 0]);
            acc[8 + 4 * a + 1] = f2fma(ps0, zy, acc[8 + 4 * a + 1]);
            acc[8 + 4 * a + 2] = f2fma(ps1, zx, acc[8 + 4 * a + 2]);
            acc[8 + 4 * a + 3] = f2fma(ps1, zy, acc[8 + 4 * a + 3]);
            acc[16 + 2 * a + 0] = f2add(acc[16 + 2 * a + 0], ph0);
            acc[16 + 2 * a + 1] = f2add(acc[16 + 2 * a + 1], ph1);
            acc[20 + 4 * a + 0] = f2fma(ph0, zx, acc[20 + 4 * a + 0]);
            acc[20 + 4 * a + 1] = f2fma(ph0, zy, acc[20 + 4 * a + 1]);
            acc[20 + 4 * a + 2] = f2fma(ph1, zx, acc[20 + 4 * a + 2]);
            acc[20 + 4 * a + 3] = f2fma(ph1, zy, acc[20 + 4 * a + 3]);
            acc[28 + 6 * a + 0] = f2fma(ph0, zz0, acc[28 + 6 * a + 0]);
            acc[28 + 6 * a + 1] = f2fma(ph0, zz1, acc[28 + 6 * a + 1]);
            acc[28 + 6 * a + 2] = f2fma(ph0, zz2, acc[28 + 6 * a + 2]);
            acc[28 + 6 * a + 3] = f2fma(ph1, zz0, acc[28 + 6 * a + 3]);
            acc[28 + 6 * a + 4] = f2fma(ph1, zz1, acc[28 + 6 * a + 4]);
            acc[28 + 6 * a + 5] = f2fma(ph1, zz2, acc[28 + 6 * a + 5]);
            acc[40 + a] = f2add(acc[40 + a], pv);
        }
    }

    float red[NMOM];
#pragma unroll
    for (int j = 0; j < NMOM; ++j) { float a, b; f2unpack(acc[j], a, b); red[j] = a + b; }

    // scalar tail (odd K)
    if ((K & 1) && blockIdx.x == 0 && threadIdx.x == 0) {
        const float2* z2 = (const float2*)inp;
        float2 z = z2[K - 1];
        float2 p = z2[2 * K - 1];
        float u0 = fmaf(sTh[6], z.x, fmaf(sTh[7], z.y, sTh[10]));
        float u1 = fmaf(sTh[8], z.x, fmaf(sTh[9], z.y, sTh[11]));
        float h0 = ftanh(u0), h1 = ftanh(u1);
        float s0 = fmaf(-h0, h0, 1.f), s1 = fmaf(-h1, h1, 1.f);
        float hs0 = h0 * s0, hs1 = h1 * s1;
        float zz0 = z.x * z.x, zz1 = z.x * z.y, zz2 = z.y * z.y;
        float pvv[2] = {p.x, p.y};
#pragma unroll
        for (int a = 0; a < 2; ++a) {
            float pa = pvv[a];
            float ps0 = pa * s0, ps1 = pa * s1, ph0 = pa * hs0, ph1 = pa * hs1;
            red[2 * a + 0] += pa * h0; red[2 * a + 1] += pa * h1;
            red[4 + 2 * a + 0] += ps0; red[4 + 2 * a + 1] += ps1;
            red[8 + 4 * a + 0] += ps0 * z.x; red[8 + 4 * a + 1] += ps0 * z.y;
            red[8 + 4 * a + 2] += ps1 * z.x; red[8 + 4 * a + 3] += ps1 * z.y;
            red[16 + 2 * a + 0] += ph0; red[16 + 2 * a + 1] += ph1;
            red[20 + 4 * a + 0] += ph0 * z.x; red[20 + 4 * a + 1] += ph0 * z.y;
            red[20 + 4 * a + 2] += ph1 * z.x; red[20 + 4 * a + 3] += ph1 * z.y;
            red[28 + 6 * a + 0] += ph0 * zz0; red[28 + 6 * a + 1] += ph0 * zz1;
            red[28 + 6 * a + 2] += ph0 * zz2; red[28 + 6 * a + 3] += ph1 * zz0;
            red[28 + 6 * a + 4] += ph1 * zz1; red[28 + 6 * a + 5] += ph1 * zz2;
            red[40 + a] += pa;
        }
    }

#pragma unroll
    for (int j = 0; j < NMOM; ++j) {
#pragma unroll
        for (int off = 16; off > 0; off >>= 1)
            red[j] += __shfl_down_sync(0xffffffffu, red[j], off);
    }
    if ((threadIdx.x & 31) == 0) {
#pragma unroll
        for (int j = 0; j < NMOM; ++j) atomicAdd(&sred[j], red[j]);
    }
    __syncthreads();
    if (threadIdx.x < NMOM) atomicAdd(&gM[k][threadIdx.x], sred[threadIdx.x]);
}

// ---------------- backward: 12-dim adjoint recursion from stored moments ----------------
__global__ void backward_kernel(const float* __restrict__ invK,
                                const float* __restrict__ invKb, int K) {
    if (blockIdx.x != 0 || threadIdx.x != 0) return;
    const float inv2K = 0.5f / (float)K;
    float lam[12];
    compute_G(gTheta[NIT], gM[NIT], invK, invKb, inv2K, lam);
    for (int k = NIT - 1; k >= 0; --k) {
#pragma unroll
        for (int j = 0; j < 12; ++j) gLam[k][j] = lam[j];
        if (k > 0) {
            const float* M = gM[k];
            const float* th = gTheta[k];
            float y[12], t4[4], tb[2];
            sym4mv(invK, lam, t4);       y[0]=t4[0]; y[1]=t4[1]; y[2]=t4[2]; y[3]=t4[3];
            sym2mv(invKb, lam + 4, tb);  y[4]=tb[0]; y[5]=tb[1];
            sym4mv(invK, lam + 6, t4);   y[6]=t4[0]; y[7]=t4[1]; y[8]=t4[2]; y[9]=t4[3];
            sym2mv(invKb, lam + 10, tb); y[10]=tb[0]; y[11]=tb[1];

            float PL[12];
#pragma unroll
            for (int a = 0; a < 2; ++a)
#pragma unroll
                for (int b = 0; b < 2; ++b)
                    PL[2 * a + b] = M[8 + 4 * a + 2 * b + 0] * lam[6 + 2 * b + 0]
                                  + M[8 + 4 * a + 2 * b + 1] * lam[6 + 2 * b + 1]
                                  + M[4 + 2 * a + b] * lam[10 + b];
            PL[4] = 0.f; PL[5] = 0.f;

            float T4[2], T5[4], T6[6];
#pragma unroll
            for (int b = 0; b < 2; ++b) {
                T4[b] = th[b] * M[16 + b] + th[2 + b] * M[16 + 2 + b];
#pragma unroll
                for (int c = 0; c < 2; ++c)
                    T5[2 * b + c] = th[b] * M[20 + 2 * b + c] + th[2 + b] * M[20 + 4 + 2 * b + c];
#pragma unroll
                for (int t6 = 0; t6 < 3; ++t6)
                    T6[3 * b + t6] = th[b] * M[28 + 3 * b + t6] + th[2 + b] * M[28 + 3 * (2 + b) + t6];
            }
#pragma unroll
            for (int b = 0; b < 2; ++b)
#pragma unroll
                for (int c = 0; c < 2; ++c) {
                    float v = lam[b] * M[8 + 2 * b + c] + lam[2 + b] * M[8 + 4 + 2 * b + c];
                    v -= 2.f * (T6[3 * b + c + 0] * lam[6 + 2 * b + 0] +
                                T6[3 * b + c + 1] * lam[6 + 2 * b + 1]);
                    v -= 2.f * T5[2 * b + c] * lam[10 + b];
                    PL[6 + 2 * b + c] = v;
                }
#pragma unroll
            for (int b = 0; b < 2; ++b) {
                float v = lam[b] * M[4 + b] + lam[2 + b] * M[4 + 2 + b];
                v -= 2.f * (T5[2 * b + 0] * lam[6 + 2 * b + 0] +
                            T5[2 * b + 1] * lam[6 + 2 * b + 1]);
                v -= 2.f * T4[b] * lam[10 + b];
                PL[10 + b] = v;
            }
#pragma unroll
            for (int j = 0; j < 12; ++j) lam[j] -= LRATE * (y[j] - inv2K * PL[j]);
        }
    }
}

// ---------------- phase C: packed dot_p reconstruction + advects ----------------
__global__ void __launch_bounds__(256)
phasec_kernel(const float* __restrict__ inp, float* __restrict__ out, int K) {
    __shared__ u64 sTh2[(NIT + 1) * 12];
    __shared__ u64 sLam2[NIT * 12];
    for (int j = threadIdx.x; j < (NIT + 1) * 12; j += blockDim.x)
        sTh2[j] = f2bcast(((const float*)gTheta)[j]);
    for (int j = threadIdx.x; j < NIT * 12; j += blockDim.x)
        sLam2[j] = f2bcast(((const float*)gLam)[j]);
    __syncthreads();

    const int npair = K >> 1;
    const float inv2K = 0.5f / (float)K;
    int t = blockIdx.x * blockDim.x + threadIdx.x;

    if (t < npair) {
        const float4* q4 = (const float4*)inp;
        const float4* p4 = (const float4*)(inp + 2 * (size_t)K);
        const float4* x4 = (const float4*)(inp + 4 * (size_t)K);
        float4 qa = q4[t], pp = p4[t];
        u64 zx = f2pack(qa.x, qa.z), zy = f2pack(qa.y, qa.w);
        u64 px = f2pack(pp.x, pp.z), py = f2pack(pp.y, pp.w);
        u64 ax = 0ULL, ay = 0ULL;
        const u64 one2 = f2bcast(1.f), negtwo2 = f2bcast(-2.f);

        for (int kk = 0; kk < NIT; ++kk) {
            const u64* th = &sTh2[12 * kk];
            const u64* L = &sLam2[12 * kk];
            u64 u0 = f2fma(th[6], zx, f2fma(th[7], zy, th[10]));
            u64 u1 = f2fma(th[8], zx, f2fma(th[9], zy, th[11]));
            u64 h0 = ftanh2(u0), h1 = ftanh2(u1);
            u64 s0 = f2fma(f2neg(h0), h0, one2), s1 = f2fma(f2neg(h1), h1, one2);
            u64 w0 = f2fma(th[0], px, f2mul(th[2], py));
            u64 w1 = f2fma(th[1], px, f2mul(th[3], py));
            u64 m0 = f2fma(L[0], px, f2mul(L[2], py));
            u64 m1 = f2fma(L[1], px, f2mul(L[3], py));
            u64 k0 = f2fma(L[6], zx, f2fma(L[7], zy, L[10]));
            u64 k1 = f2fma(L[8], zx, f2fma(L[9], zy, L[11]));
            u64 wh0 = f2mul(w0, h0), wh1 = f2mul(w1, h1);
            u64 e0 = f2mul(s0, f2fma(f2mul(negtwo2, wh0), k0, m0));
            u64 e1 = f2mul(s1, f2fma(f2mul(negtwo2, wh1), k1, m1));
            u64 ws0 = f2mul(w0, s0), ws1 = f2mul(w1, s1);
            ax = f2fma(e0, th[6], ax); ax = f2fma(e1, th[8], ax);
            ax = f2fma(L[6], ws0, ax); ax = f2fma(L[8], ws1, ax);
            ay = f2fma(e0, th[7], ay); ay = f2fma(e1, th[9], ay);
            ay = f2fma(L[7], ws0, ay); ay = f2fma(L[9], ws1, ay);
        }

        const u64* th = &sTh2[12 * NIT];
        u64 u0 = f2fma(th[6], zx, f2fma(th[7], zy, th[10]));
        u64 u1 = f2fma(th[8], zx, f2fma(th[9], zy, th[11]));
        u64 h0 = ftanh2(u0), h1 = ftanh2(u1);
        u64 s0 = f2fma(f2neg(h0), h0, one2), s1 = f2fma(f2neg(h1), h1, one2);
        u64 w0 = f2fma(th[0], px, f2mul(th[2], py));
        u64 w1 = f2fma(th[1], px, f2mul(th[3], py));
        u64 ws0 = f2mul(w0, s0), ws1 = f2mul(w1, s1);
        const u64 lr2 = f2bcast(LRATE), i2k = f2bcast(inv2K);
        u64 dpx = f2mul(i2k, f2fma(lr2, ax, f2neg(f2fma(ws0, th[6], f2mul(ws1, th[8])))));
        u64 dpy = f2mul(i2k, f2fma(lr2, ay, f2neg(f2fma(ws0, th[7], f2mul(ws1, th[9])))));
        u64 dqx = f2fma(th[0], h0, f2fma(th[1], h1, th[4]));
        u64 dqy = f2fma(th[2], h0, f2fma(th[3], h1, th[5]));
        float4 xv = x4[t];
        u64 xx = f2pack(xv.x, xv.z), xy = f2pack(xv.y, xv.w);
        u64 v0 = f2fma(th[6], xx, f2fma(th[7], xy, th[10]));
        u64 v1 = f2fma(th[8], xx, f2fma(th[9], xy, th[11]));
        u64 g0 = ftanh2(v0), g1 = ftanh2(v1);
        u64 dxx = f2fma(th[0], g0, f2fma(th[1], g1, th[4]));
        u64 dxy = f2fma(th[2], g0, f2fma(th[3], g1, th[5]));

        float4* o4 = (float4*)out;
        float a0, a1, b0, b1;
        f2unpack(dqx, a0, a1); f2unpack(dqy, b0, b1);
        o4[t] = make_float4(a0, b0, a1, b1);
        f2unpack(dpx, a0, a1); f2unpack(dpy, b0, b1);
        o4[t + npair] = make_float4(a0, b0, a1, b1);
        f2unpack(dxx, a0, a1); f2unpack(dxy, b0, b1);
        o4[t + 2 * npair] = make_float4(a0, b0, a1, b1);
    } else if ((K & 1) && t == npair) {
        // scalar tail for odd K: full scalar path for point K-1
        const float2* z2 = (const float2*)inp;
        float2* o2 = (float2*)out;
        int i = K - 1;
        float zx = z2[i].x, zy = z2[i].y;
        float pxx = z2[K + i].x, pyy = z2[K + i].y;
        float axs = 0.f, ays = 0.f;
        for (int kk = 0; kk < NIT; ++kk) {
            const float* th = gTheta[kk];
            const float* L = gLam[kk];
            float u0 = fmaf(th[6], zx, fmaf(th[7], zy, th[10]));
            float u1 = fmaf(th[8], zx, fmaf(th[9], zy, th[11]));
            float h0 = ftanh(u0), h1 = ftanh(u1);
            float s0 = fmaf(-h0, h0, 1.f), s1 = fmaf(-h1, h1, 1.f);
            float w0 = fmaf(th[0], pxx, th[2] * pyy);
            float w1 = fmaf(th[1], pxx, th[3] * pyy);
            float m0 = fmaf(L[0], pxx, L[2] * pyy);
            float m1 = fmaf(L[1], pxx, L[3] * pyy);
            float k0 = fmaf(L[6], zx, fmaf(L[7], zy, L[10]));
            float k1 = fmaf(L[8], zx, fmaf(L[9], zy, L[11]));
            float e0 = s0 * fmaf(-2.f * w0 * h0, k0, m0);
            float e1 = s1 * fmaf(-2.f * w1 * h1, k1, m1);
            float ws0 = w0 * s0, ws1 = w1 * s1;
            axs += e0 * th[6] + e1 * th[8] + L[6] * ws0 + L[8] * ws1;
            ays += e0 * th[7] + e1 * th[9] + L[7] * ws0 + L[9] * ws1;
        }
        const float* th = gTheta[NIT];
        float u0 = fmaf(th[6], zx, fmaf(th[7], zy, th[10]));
        float u1 = fmaf(th[8], zx, fmaf(th[9], zy, th[11]));
        float h0 = ftanh(u0), h1 = ftanh(u1);
        float s0 = fmaf(-h0, h0, 1.f), s1 = fmaf(-h1, h1, 1.f);
        float w0 = fmaf(th[0], pxx, th[2] * pyy);
        float w1 = fmaf(th[1], pxx, th[3] * pyy);
        float ws0 = w0 * s0, ws1 = w1 * s1;
        o2[i] = make_float2(fmaf(th[0], h0, fmaf(th[1], h1, th[4])),
                            fmaf(th[2], h0, fmaf(th[3], h1, th[5])));
        o2[K + i] = make_float2(inv2K * (LRATE * axs - (ws0 * th[6] + ws1 * th[8])),
                                inv2K * (LRATE * ays - (ws0 * th[7] + ws1 * th[9])));
        float xxs = z2[2 * K + i].x, xys = z2[2 * K + i].y;
        float v0 = fmaf(th[6], xxs, fmaf(th[7], xys, th[10]));
        float v1 = fmaf(th[8], xxs, fmaf(th[9], xys, th[11]));
        float g0 = ftanh(v0), g1 = ftanh(v1);
        o2[2 * K + i] = make_float2(fmaf(th[0], g0, fmaf(th[1], g1, th[4])),
                                    fmaf(th[2], g0, fmaf(th[3], g1, th[5])));
    }
}

extern "C" void kernel_launch(void* const* d_in, const int* in_sizes, int n_in,
                              void* d_out, int out_size) {
    (void)n_in; (void)out_size;
    const float* inp   = (const float*)d_in[1];
    const float* t1i   = (const float*)d_in[2];
    const float* b1i   = (const float*)d_in[3];
    const float* t2i   = (const float*)d_in[4];
    const float* b2i   = (const float*)d_in[5];
    const float* invK  = (const float*)d_in[6];
    const float* invKb = (const float*)d_in[7];
    int K = in_sizes[1] / 6;

    zero_moments_kernel<<<4, 256>>>();
    for (int k = 0; k <= NIT; ++k)
        pass_kernel<<<444, 128>>>(inp, t1i, b1i, t2i, b2i, invK, invKb, K, k);
    backward_kernel<<<1, 1>>>(invK, invKb, K);
    int threads_needed = (K >> 1) + (K & 1);
    int blocks = (threads_needed + 255) / 256;
    phasec_kernel<<<blocks, 256>>>(inp, (float*)d_out, K);
}

// round 3
// speedup vs baseline: 1.0415x; 1.0399x over previous
#include <cuda_runtime.h>

#define LRATE 0.25f
#define NIT 20
#define NMOM 42
#define MPAD 48

// Persistent device scratch (rewritten deterministically every launch)
__device__ float gM[NIT + 1][MPAD];      // moments per iteration
__device__ float gTheta[NIT + 1][12];    // theta trajectory
__device__ float gLam[NIT][12];          // adjoints: gLam[k] = lambda_{k+1}

// theta layout [12]: t1 (0..3 row-major), b1 (4,5), t2 (6..9 row-major), b2 (10,11)
// gM layout [42]:
//  0..3   M1_{ab} = sum p_a h_b
//  4..7   M2_{ab} = sum p_a s_b
//  8..15  M3_{abc}= sum p_a s_b z_c
// 16..19  M4_{ab} = sum p_a h_b s_b
// 20..27  M5_{abc}= sum p_a h_b s_b z_c
// 28..39  M6      = sum p_a h_b s_b z_c z_e (sym pair c+e)
// 40..41  Sp_a    = sum p_a   (theta-independent; only written by pass 0)

__device__ __forceinline__ float ftanh(float x) {
    float e = __expf(-2.0f * fabsf(x));
    float r = __fdividef(1.0f - e, 1.0f + e);
    return copysignf(r, x);
}

__device__ __forceinline__ void sym4mv(const float* __restrict__ A, const float* v, float* y) {
#pragma unroll
    for (int r = 0; r < 4; ++r) {
        float s = 0.f;
#pragma unroll
        for (int c = 0; c < 4; ++c) s += 0.5f * (A[4 * r + c] + A[4 * c + r]) * v[c];
        y[r] = s;
    }
}
__device__ __forceinline__ void sym2mv(const float* __restrict__ A, const float* v, float* y) {
#pragma unroll
    for (int r = 0; r < 2; ++r) {
        float s = 0.f;
#pragma unroll
        for (int c = 0; c < 2; ++c) s += 0.5f * (A[2 * r + c] + A[2 * c + r]) * v[c];
        y[r] = s;
    }
}

// G = dL/dtheta from moments M at theta th (Sp passed separately)
__device__ __forceinline__ void compute_G(const float* th, const float* M,
                                          float sp0, float sp1,
                                          const float* __restrict__ invK,
                                          const float* __restrict__ invKb,
                                          float inv2K, float* G) {
    float y[4], yb[2];
    sym4mv(invK, th, y);
#pragma unroll
    for (int r = 0; r < 4; ++r) G[r] = y[r] - inv2K * M[r];
    sym2mv(invKb, th + 4, yb);
    G[4] = yb[0] - inv2K * sp0;
    G[5] = yb[1] - inv2K * sp1;
    float v2[4] = {th[6] - 1.f, th[7], th[8], th[9] - 1.f};
    sym4mv(invK, v2, y);
#pragma unroll
    for (int b = 0; b < 2; ++b)
#pragma unroll
        for (int c = 0; c < 2; ++c) {
            float pot = th[b] * M[8 + 2 * b + c] + th[2 + b] * M[8 + 4 + 2 * b + c];
            G[6 + 2 * b + c] = y[2 * b + c] - inv2K * pot;
        }
    sym2mv(invKb, th + 10, yb);
#pragma unroll
    for (int b = 0; b < 2; ++b) {
        float pot = th[b] * M[4 + b] + th[2 + b] * M[4 + 2 + b];
        G[10 + b] = yb[b] - inv2K * pot;
    }
}

__global__ void zero_moments_kernel() {
    int t = threadIdx.x;
    if (t < (NIT + 1) * MPAD) ((float*)gM)[t] = 0.f;
}

// MODE: 0 = forward set + Sp (pass 0, 18 accums)
//       1 = full Hessian set (passes 1..19, 40 accums)
//       2 = forward set only (pass 20, 16 accums)
template <int MODE>
__global__ void __launch_bounds__(128, 5)
pass_kernel(const float* __restrict__ inp,
            const float* __restrict__ t1i, const float* __restrict__ b1i,
            const float* __restrict__ t2i, const float* __restrict__ b2i,
            const float* __restrict__ invK, const float* __restrict__ invKb,
            int K, int k) {
    constexpr int NACT = (MODE == 1) ? 40 : (MODE == 0 ? 18 : 16);
    __shared__ float sTh[12];
    __shared__ float sred[NACT];

    if (threadIdx.x == 0) {
        float th[12];
        if (k == 0) {
            th[0] = t1i[0]; th[1] = t1i[1]; th[2] = t1i[2]; th[3] = t1i[3];
            th[4] = b1i[0]; th[5] = b1i[1];
            th[6] = t2i[0]; th[7] = t2i[1]; th[8] = t2i[2]; th[9] = t2i[3];
            th[10] = b2i[0]; th[11] = b2i[1];
        } else {
            float pth[12], G[12];
#pragma unroll
            for (int j = 0; j < 12; ++j) pth[j] = gTheta[k - 1][j];
            compute_G(pth, gM[k - 1], gM[0][40], gM[0][41], invK, invKb,
                      0.5f / (float)K, G);
#pragma unroll
            for (int j = 0; j < 12; ++j) th[j] = pth[j] - LRATE * G[j];
        }
#pragma unroll
        for (int j = 0; j < 12; ++j) { sTh[j] = th[j]; gTheta[k][j] = th[j]; }
    }
    if (threadIdx.x < NACT) sred[threadIdx.x] = 0.f;
    __syncthreads();

    const float c20 = sTh[6], c21 = sTh[7], c22 = sTh[8], c23 = sTh[9];
    const float d0 = sTh[10], d1 = sTh[11];

    float acc[NACT];
#pragma unroll
    for (int j = 0; j < NACT; ++j) acc[j] = 0.f;

    const float4* q4 = (const float4*)inp;
    const float4* p4 = (const float4*)(inp + 2 * (size_t)K);
    const int nquad = K >> 2;
    const int stride = gridDim.x * blockDim.x;

    for (int t = blockIdx.x * blockDim.x + threadIdx.x; t < nquad; t += stride) {
        float4 qa = q4[2 * t], qb = q4[2 * t + 1];
        float4 pa4 = p4[2 * t], pb4 = p4[2 * t + 1];
        float ZX[4] = {qa.x, qa.z, qb.x, qb.z};
        float ZY[4] = {qa.y, qa.w, qb.y, qb.w};
        float PX[4] = {pa4.x, pa4.z, pb4.x, pb4.z};
        float PY[4] = {pa4.y, pa4.w, pb4.y, pb4.w};
#pragma unroll
        for (int m = 0; m < 4; ++m) {
            float zx = ZX[m], zy = ZY[m];
            float u0 = fmaf(c20, zx, fmaf(c21, zy, d0));
            float u1 = fmaf(c22, zx, fmaf(c23, zy, d1));
            float h0 = ftanh(u0), h1 = ftanh(u1);
            float s0 = fmaf(-h0, h0, 1.f), s1 = fmaf(-h1, h1, 1.f);
            float s0zx = s0 * zx, s0zy = s0 * zy;
            float s1zx = s1 * zx, s1zy = s1 * zy;
            float pv[2] = {PX[m], PY[m]};
#pragma unroll
            for (int a = 0; a < 2; ++a) {
                float p = pv[a];
                acc[0 + 2 * a + 0] = fmaf(p, h0, acc[0 + 2 * a + 0]);
                acc[0 + 2 * a + 1] = fmaf(p, h1, acc[0 + 2 * a + 1]);
                acc[4 + 2 * a + 0] = fmaf(p, s0, acc[4 + 2 * a + 0]);
                acc[4 + 2 * a + 1] = fmaf(p, s1, acc[4 + 2 * a + 1]);
                acc[8 + 4 * a + 0] = fmaf(p, s0zx, acc[8 + 4 * a + 0]);
                acc[8 + 4 * a + 1] = fmaf(p, s0zy, acc[8 + 4 * a + 1]);
                acc[8 + 4 * a + 2] = fmaf(p, s1zx, acc[8 + 4 * a + 2]);
                acc[8 + 4 * a + 3] = fmaf(p, s1zy, acc[8 + 4 * a + 3]);
            }
            if (MODE == 1) {
                float hs0 = h0 * s0, hs1 = h1 * s1;
                float hs0zx = hs0 * zx, hs0zy = hs0 * zy;
                float hs1zx = hs1 * zx, hs1zy = hs1 * zy;
                float h600 = hs0zx * zx, h601 = hs0zx * zy, h602 = hs0zy * zy;
                float h610 = hs1zx * zx, h611 = hs1zx * zy, h612 = hs1zy * zy;
#pragma unroll
                for (int a = 0; a < 2; ++a) {
                    float p = pv[a];
                    acc[16 + 2 * a + 0] = fmaf(p, hs0, acc[16 + 2 * a + 0]);
                    acc[16 + 2 * a + 1] = fmaf(p, hs1, acc[16 + 2 * a + 1]);
                    acc[20 + 4 * a + 0] = fmaf(p, hs0zx, acc[20 + 4 * a + 0]);
                    acc[20 + 4 * a + 1] = fmaf(p, hs0zy, acc[20 + 4 * a + 1]);
                    acc[20 + 4 * a + 2] = fmaf(p, hs1zx, acc[20 + 4 * a + 2]);
                    acc[20 + 4 * a + 3] = fmaf(p, hs1zy, acc[20 + 4 * a + 3]);
                    acc[28 + 6 * a + 0] = fmaf(p, h600, acc[28 + 6 * a + 0]);
                    acc[28 + 6 * a + 1] = fmaf(p, h601, acc[28 + 6 * a + 1]);
                    acc[28 + 6 * a + 2] = fmaf(p, h602, acc[28 + 6 * a + 2]);
                    acc[28 + 6 * a + 3] = fmaf(p, h610, acc[28 + 6 * a + 3]);
                    acc[28 + 6 * a + 4] = fmaf(p, h611, acc[28 + 6 * a + 4]);
                    acc[28 + 6 * a + 5] = fmaf(p, h612, acc[28 + 6 * a + 5]);
                }
            }
            if (MODE == 0) {
                acc[16] += PX[m];
                acc[17] += PY[m];
            }
        }
    }

    // scalar tail for K % 4 (dead for K = 2^20, kept for generality)
    if ((K & 3) && blockIdx.x == 0 && threadIdx.x == 0) {
        const float2* z2 = (const float2*)inp;
        for (int i = K & ~3; i < K; ++i) {
            float2 z = z2[i];
            float2 p2 = z2[K + i];
            float u0 = fmaf(c20, z.x, fmaf(c21, z.y, d0));
            float u1 = fmaf(c22, z.x, fmaf(c23, z.y, d1));
            float h0 = ftanh(u0), h1 = ftanh(u1);
            float s0 = fmaf(-h0, h0, 1.f), s1 = fmaf(-h1, h1, 1.f);
            float s0zx = s0 * z.x, s0zy = s0 * z.y;
            float s1zx = s1 * z.x, s1zy = s1 * z.y;
            float pvv[2] = {p2.x, p2.y};
#pragma unroll
            for (int a = 0; a < 2; ++a) {
                float p = pvv[a];
                acc[2 * a + 0] += p * h0; acc[2 * a + 1] += p * h1;
                acc[4 + 2 * a + 0] += p * s0; acc[4 + 2 * a + 1] += p * s1;
                acc[8 + 4 * a + 0] += p * s0zx; acc[8 + 4 * a + 1] += p * s0zy;
                acc[8 + 4 * a + 2] += p * s1zx; acc[8 + 4 * a + 3] += p * s1zy;
            }
            if (MODE == 1) {
                float hs0 = h0 * s0, hs1 = h1 * s1;
#pragma unroll
                for (int a = 0; a < 2; ++a) {
                    float p = pvv[a];
                    acc[16 + 2 * a + 0] += p * hs0;
                    acc[16 + 2 * a + 1] += p * hs1;
                    acc[20 + 4 * a + 0] += p * hs0 * z.x;
                    acc[20 + 4 * a + 1] += p * hs0 * z.y;
                    acc[20 + 4 * a + 2] += p * hs1 * z.x;
                    acc[20 + 4 * a + 3] += p * hs1 * z.y;
                    acc[28 + 6 * a + 0] += p * hs0 * z.x * z.x;
                    acc[28 + 6 * a + 1] += p * hs0 * z.x * z.y;
                    acc[28 + 6 * a + 2] += p * hs0 * z.y * z.y;
                    acc[28 + 6 * a + 3] += p * hs1 * z.x * z.x;
                    acc[28 + 6 * a + 4] += p * hs1 * z.x * z.y;
                    acc[28 + 6 * a + 5] += p * hs1 * z.y * z.y;
                }
            }
            if (MODE == 0) { acc[16] += p2.x; acc[17] += p2.y; }
        }
    }

#pragma unroll
    for (int j = 0; j < NACT; ++j) {
#pragma unroll
        for (int off = 16; off > 0; off >>= 1)
            acc[j] += __shfl_down_sync(0xffffffffu, acc[j], off);
    }
    if ((threadIdx.x & 31) == 0) {
#pragma unroll
        for (int j = 0; j < NACT; ++j) atomicAdd(&sred[j], acc[j]);
    }
    __syncthreads();
    if (threadIdx.x < NACT) {
        int g = (MODE == 0 && threadIdx.x >= 16) ? (40 + threadIdx.x - 16) : threadIdx.x;
        atomicAdd(&gM[k][g], sred[threadIdx.x]);
    }
}

// ---------------- backward: 12-dim adjoint recursion ----------------
__global__ void backward_kernel(const float* __restrict__ invK,
                                const float* __restrict__ invKb, int K) {
    if (blockIdx.x != 0 || threadIdx.x != 0) return;
    const float inv2K = 0.5f / (float)K;
    float lam[12];
    compute_G(gTheta[NIT], gM[NIT], gM[0][40], gM[0][41], invK, invKb, inv2K, lam);
    for (int k = NIT - 1; k >= 0; --k) {
#pragma unroll
        for (int j = 0; j < 12; ++j) gLam[k][j] = lam[j];
        if (k > 0) {
            const float* M = gM[k];
            const float* th = gTheta[k];
            float y[12], t4[4], tb[2];
            sym4mv(invK, lam, t4);       y[0]=t4[0]; y[1]=t4[1]; y[2]=t4[2]; y[3]=t4[3];
            sym2mv(invKb, lam + 4, tb);  y[4]=tb[0]; y[5]=tb[1];
            sym4mv(invK, lam + 6, t4);   y[6]=t4[0]; y[7]=t4[1]; y[8]=t4[2]; y[9]=t4[3];
            sym2mv(invKb, lam + 10, tb); y[10]=tb[0]; y[11]=tb[1];

            float PL[12];
#pragma unroll
            for (int a = 0; a < 2; ++a)
#pragma unroll
                for (int b = 0; b < 2; ++b)
                    PL[2 * a + b] = M[8 + 4 * a + 2 * b + 0] * lam[6 + 2 * b + 0]
                                  + M[8 + 4 * a + 2 * b + 1] * lam[6 + 2 * b + 1]
                                  + M[4 + 2 * a + b] * lam[10 + b];
            PL[4] = 0.f; PL[5] = 0.f;

            float T4[2], T5[4], T6[6];
#pragma unroll
            for (int b = 0; b < 2; ++b) {
                T4[b] = th[b] * M[16 + b] + th[2 + b] * M[16 + 2 + b];
#pragma unroll
                for (int c = 0; c < 2; ++c)
                    T5[2 * b + c] = th[b] * M[20 + 2 * b + c] + th[2 + b] * M[20 + 4 + 2 * b + c];
#pragma unroll
                for (int t6 = 0; t6 < 3; ++t6)
                    T6[3 * b + t6] = th[b] * M[28 + 3 * b + t6] + th[2 + b] * M[28 + 3 * (2 + b) + t6];
            }
#pragma unroll
            for (int b = 0; b < 2; ++b)
#pragma unroll
                for (int c = 0; c < 2; ++c) {
                    float v = lam[b] * M[8 + 2 * b + c] + lam[2 + b] * M[8 + 4 + 2 * b + c];
                    v -= 2.f * (T6[3 * b + c + 0] * lam[6 + 2 * b + 0] +
                                T6[3 * b + c + 1] * lam[6 + 2 * b + 1]);
                    v -= 2.f * T5[2 * b + c] * lam[10 + b];
                    PL[6 + 2 * b + c] = v;
                }
#pragma unroll
            for (int b = 0; b < 2; ++b) {
                float v = lam[b] * M[4 + b] + lam[2 + b] * M[4 + 2 + b];
                v -= 2.f * (T5[2 * b + 0] * lam[6 + 2 * b + 0] +
                            T5[2 * b + 1] * lam[6 + 2 * b + 1]);
                v -= 2.f * T4[b] * lam[10 + b];
                PL[10 + b] = v;
            }
#pragma unroll
            for (int j = 0; j < 12; ++j) lam[j] -= LRATE * (y[j] - inv2K * PL[j]);
        }
    }
}

// ---------------- phase C: dot_p reconstruction + advects, 2 pts/thread ----------------
__global__ void __launch_bounds__(256)
phasec_kernel(const float* __restrict__ inp, float* __restrict__ out, int K) {
    __shared__ float sTh[(NIT + 1) * 12];
    __shared__ float sLam[NIT * 12];
    for (int j = threadIdx.x; j < (NIT + 1) * 12; j += blockDim.x)
        sTh[j] = ((const float*)gTheta)[j];
    for (int j = threadIdx.x; j < NIT * 12; j += blockDim.x)
        sLam[j] = ((const float*)gLam)[j];
    __syncthreads();

    const int npair = K >> 1;
    const float inv2K = 0.5f / (float)K;
    int t = blockIdx.x * blockDim.x + threadIdx.x;

    if (t < npair) {
        const float4* q4 = (const float4*)inp;
        const float4* p4 = (const float4*)(inp + 2 * (size_t)K);
        const float4* x4 = (const float4*)(inp + 4 * (size_t)K);
        float4 qa = q4[t], pp = p4[t];
        float zx0 = qa.x, zy0 = qa.y, zx1 = qa.z, zy1 = qa.w;
        float px0 = pp.x, py0 = pp.y, px1 = pp.z, py1 = pp.w;
        float ax0 = 0.f, ay0 = 0.f, ax1 = 0.f, ay1 = 0.f;

#pragma unroll
        for (int kk = 0; kk < NIT; ++kk) {
            const float* th = &sTh[12 * kk];
            const float* L = &sLam[12 * kk];
            float a0 = th[0], a1 = th[1], a2 = th[2], a3 = th[3];
            float c0 = th[6], c1 = th[7], c2 = th[8], c3 = th[9];
            float d0 = th[10], d1 = th[11];
            float l0 = L[0], l1 = L[1], l2 = L[2], l3 = L[3];
            float q0 = L[6], q1 = L[7], q2 = L[8], q3 = L[9];
            float r0 = L[10], r1 = L[11];
            // point 0
            {
                float u0 = fmaf(c0, zx0, fmaf(c1, zy0, d0));
                float u1 = fmaf(c2, zx0, fmaf(c3, zy0, d1));
                float h0 = ftanh(u0), h1 = ftanh(u1);
                float s0 = fmaf(-h0, h0, 1.f), s1 = fmaf(-h1, h1, 1.f);
                float w0 = fmaf(a0, px0, a2 * py0);
                float w1 = fmaf(a1, px0, a3 * py0);
                float m0 = fmaf(l0, px0, l2 * py0);
                float m1 = fmaf(l1, px0, l3 * py0);
                float k0 = fmaf(q0, zx0, fmaf(q1, zy0, r0));
                float k1 = fmaf(q2, zx0, fmaf(q3, zy0, r1));
                float e0 = s0 * fmaf(-2.f * w0 * h0, k0, m0);
                float e1 = s1 * fmaf(-2.f * w1 * h1, k1, m1);
                float ws0 = w0 * s0, ws1 = w1 * s1;
                ax0 = fmaf(e0, c0, fmaf(e1, c2, fmaf(q0, ws0, fmaf(q2, ws1, ax0))));
                ay0 = fmaf(e0, c1, fmaf(e1, c3, fmaf(q1, ws0, fmaf(q3, ws1, ay0))));
            }
            // point 1
            {
                float u0 = fmaf(c0, zx1, fmaf(c1, zy1, d0));
                float u1 = fmaf(c2, zx1, fmaf(c3, zy1, d1));
                float h0 = ftanh(u0), h1 = ftanh(u1);
                float s0 = fmaf(-h0, h0, 1.f), s1 = fmaf(-h1, h1, 1.f);
                float w0 = fmaf(a0, px1, a2 * py1);
                float w1 = fmaf(a1, px1, a3 * py1);
                float m0 = fmaf(l0, px1, l2 * py1);
                float m1 = fmaf(l1, px1, l3 * py1);
                float k0 = fmaf(q0, zx1, fmaf(q1, zy1, r0));
                float k1 = fmaf(q2, zx1, fmaf(q3, zy1, r1));
                float e0 = s0 * fmaf(-2.f * w0 * h0, k0, m0);
                float e1 = s1 * fmaf(-2.f * w1 * h1, k1, m1);
                float ws0 = w0 * s0, ws1 = w1 * s1;
                ax1 = fmaf(e0, c0, fmaf(e1, c2, fmaf(q0, ws0, fmaf(q2, ws1, ax1))));
                ay1 = fmaf(e0, c1, fmaf(e1, c3, fmaf(q1, ws0, fmaf(q3, ws1, ay1))));
            }
        }

        const float* th = &sTh[12 * NIT];
        float a0 = th[0], a1 = th[1], a2 = th[2], a3 = th[3], b0 = th[4], b1v = th[5];
        float c0 = th[6], c1 = th[7], c2 = th[8], c3 = th[9], d0 = th[10], d1 = th[11];
        float4 xv = x4[t];
        float4 oq, op, ox;
        {
            float u0 = fmaf(c0, zx0, fmaf(c1, zy0, d0));
            float u1 = fmaf(c2, zx0, fmaf(c3, zy0, d1));
            float h0 = ftanh(u0), h1 = ftanh(u1);
            float s0 = fmaf(-h0, h0, 1.f), s1 = fmaf(-h1, h1, 1.f);
            float w0 = fmaf(a0, px0, a2 * py0);
            float w1 = fmaf(a1, px0, a3 * py0);
            float ws0 = w0 * s0, ws1 = w1 * s1;
            oq.x = fmaf(a0, h0, fmaf(a1, h1, b0));
            oq.y = fmaf(a2, h0, fmaf(a3, h1, b1v));
            op.x = inv2K * (LRATE * ax0 - (ws0 * c0 + ws1 * c2));
            op.y = inv2K * (LRATE * ay0 - (ws0 * c1 + ws1 * c3));
        }
        {
            float u0 = fmaf(c0, zx1, fmaf(c1, zy1, d0));
            float u1 = fmaf(c2, zx1, fmaf(c3, zy1, d1));
            float h0 = ftanh(u0), h1 = ftanh(u1);
            float s0 = fmaf(-h0, h0, 1.f), s1 = fmaf(-h1, h1, 1.f);
            float w0 = fmaf(a0, px1, a2 * py1);
            float w1 = fmaf(a1, px1, a3 * py1);
            float ws0 = w0 * s0, ws1 = w1 * s1;
            oq.z = fmaf(a0, h0, fmaf(a1, h1, b0));
            oq.w = fmaf(a2, h0, fmaf(a3, h1, b1v));
            op.z = inv2K * (LRATE * ax1 - (ws0 * c0 + ws1 * c2));
            op.w = inv2K * (LRATE * ay1 - (ws0 * c1 + ws1 * c3));
        }
        {
            float v0 = fmaf(c0, xv.x, fmaf(c1, xv.y, d0));
            float v1 = fmaf(c2, xv.x, fmaf(c3, xv.y, d1));
            float g0 = ftanh(v0), g1 = ftanh(v1);
            ox.x = fmaf(a0, g0, fmaf(a1, g1, b0));
            ox.y = fmaf(a2, g0, fmaf(a3, g1, b1v));
            float v2 = fmaf(c0, xv.z, fmaf(c1, xv.w, d0));
            float v3 = fmaf(c2, xv.z, fmaf(c3, xv.w, d1));
            float g2 = ftanh(v2), g3 = ftanh(v3);
            ox.z = fmaf(a0, g2, fmaf(a1, g3, b0));
            ox.w = fmaf(a2, g2, fmaf(a3, g3, b1v));
        }
        float4* o4 = (float4*)out;
        o4[t] = oq;
        o4[t + npair] = op;
        o4[t + 2 * npair] = ox;
    } else if ((K & 1) && t == npair) {
        // scalar tail (odd K)
        const float2* z2 = (const float2*)inp;
        float2* o2 = (float2*)out;
        int i = K - 1;
        float zx = z2[i].x, zy = z2[i].y;
        float pxx = z2[K + i].x, pyy = z2[K + i].y;
        float axs = 0.f, ays = 0.f;
        for (int kk = 0; kk < NIT; ++kk) {
            const float* th = &sTh[12 * kk];
            const float* L = &sLam[12 * kk];
            float u0 = fmaf(th[6], zx, fmaf(th[7], zy, th[10]));
            float u1 = fmaf(th[8], zx, fmaf(th[9], zy, th[11]));
            float h0 = ftanh(u0), h1 = ftanh(u1);
            float s0 = fmaf(-h0, h0, 1.f), s1 = fmaf(-h1, h1, 1.f);
            float w0 = fmaf(th[0], pxx, th[2] * pyy);
            float w1 = fmaf(th[1], pxx, th[3] * pyy);
            float m0 = fmaf(L[0], pxx, L[2] * pyy);
            float m1 = fmaf(L[1], pxx, L[3] * pyy);
            float k0 = fmaf(L[6], zx, fmaf(L[7], zy, L[10]));
            float k1 = fmaf(L[8], zx, fmaf(L[9], zy, L[11]));
            float e0 = s0 * fmaf(-2.f * w0 * h0, k0, m0);
            float e1 = s1 * fmaf(-2.f * w1 * h1, k1, m1);
            float ws0 = w0 * s0, ws1 = w1 * s1;
            axs += e0 * th[6] + e1 * th[8] + L[6] * ws0 + L[8] * ws1;
            ays += e0 * th[7] + e1 * th[9] + L[7] * ws0 + L[9] * ws1;
        }
        const float* th = &sTh[12 * NIT];
        float u0 = fmaf(th[6], zx, fmaf(th[7], zy, th[10]));
        float u1 = fmaf(th[8], zx, fmaf(th[9], zy, th[11]));
        float h0 = ftanh(u0), h1 = ftanh(u1);
        float s0 = fmaf(-h0, h0, 1.f), s1 = fmaf(-h1, h1, 1.f);
        float w0 = fmaf(th[0], pxx, th[2] * pyy);
        float w1 = fmaf(th[1], pxx, th[3] * pyy);
        float ws0 = w0 * s0, ws1 = w1 * s1;
        o2[i] = make_float2(fmaf(th[0], h0, fmaf(th[1], h1, th[4])),
                            fmaf(th[2], h0, fmaf(th[3], h1, th[5])));
        o2[K + i] = make_float2(inv2K * (LRATE * axs - (ws0 * th[6] + ws1 * th[8])),
                                inv2K * (LRATE * ays - (ws0 * th[7] + ws1 * th[9])));
        float xxs = z2[2 * K + i].x, xys = z2[2 * K + i].y;
        float v0 = fmaf(th[6], xxs, fmaf(th[7], xys, th[10]));
        float v1 = fmaf(th[8], xxs, fmaf(th[9], xys, th[11]));
        float g0 = ftanh(v0), g1 = ftanh(v1);
        o2[2 * K + i] = make_float2(fmaf(th[0], g0, fmaf(th[1], g1, th[4])),
                                    fmaf(th[2], g0, fmaf(th[3], g1, th[5])));
    }
}

extern "C" void kernel_launch(void* const* d_in, const int* in_sizes, int n_in,
                              void* d_out, int out_size) {
    (void)n_in; (void)out_size;
    const float* inp   = (const float*)d_in[1];
    const float* t1i   = (const float*)d_in[2];
    const float* b1i   = (const float*)d_in[3];
    const float* t2i   = (const float*)d_in[4];
    const float* b2i   = (const float*)d_in[5];
    const float* invK  = (const float*)d_in[6];
    const float* invKb = (const float*)d_in[7];
    int K = in_sizes[1] / 6;

    zero_moments_kernel<<<1, 1024>>>();
    const int PB = 740;   // 5 blocks/SM * 148
    const int PT = 128;
    pass_kernel<0><<<PB, PT>>>(inp, t1i, b1i, t2i, b2i, invK, invKb, K, 0);
    for (int k = 1; k < NIT; ++k)
        pass_kernel<1><<<PB, PT>>>(inp, t1i, b1i, t2i, b2i, invK, invKb, K, k);
    pass_kernel<2><<<PB, PT>>>(inp, t1i, b1i, t2i, b2i, invK, invKb, K, NIT);
    backward_kernel<<<1, 1>>>(invK, invKb, K);
    int threads_needed = (K >> 1) + (K & 1);
    int blocks = (threads_needed + 255) / 256;
    phasec_kernel<<<blocks, 256>>>(inp, (float*)d_out, K);
}